// round 1
// baseline (speedup 1.0000x reference)
#include <cuda_runtime.h>

#define EPSF 1e-9f

static constexpr int N = 4;           // n1 == n2 == 4
static constexpr int D = 4608;
static constexpr int D4 = D / 4;      // 1152 float4 per row
static constexpr int THREADS = 384;
static constexpr int ITERS = D4 / THREADS;  // 3
static constexpr int NWARP = THREADS / 32;  // 12
static constexpr int NACC = N + N * N;      // 20 accumulators

__global__ __launch_bounds__(THREADS)
void negkl_kernel(const float4* __restrict__ in1, const float4* __restrict__ m1,
                  const float4* __restrict__ in2, const float4* __restrict__ m2,
                  float* __restrict__ out)
{
    const int b = blockIdx.x;
    const int t = threadIdx.x;
    const size_t base = (size_t)b * N * D4;
    const float4* P  = in1 + base;
    const float4* M1 = m1  + base;
    const float4* Q  = in2 + base;
    const float4* M2 = m2  + base;

    // ent[i] = sum_d p_i * log2(p_i + eps)
    // cross[i][j] = sum_d p_i * log2(q_j + eps)
    // final: out[b,i,j] = (cross[i][j] - ent[i]) * ln2   (== -div)
    float ent[N];
    float cross[N][N];
#pragma unroll
    for (int i = 0; i < N; i++) {
        ent[i] = 0.f;
#pragma unroll
        for (int j = 0; j < N; j++) cross[i][j] = 0.f;
    }

#pragma unroll
    for (int it = 0; it < ITERS; it++) {
        const int dc = it * THREADS + t;
        float4 p[N];
#pragma unroll
        for (int i = 0; i < N; i++) {
            float4 v = P[i * D4 + dc];
            float4 m = M1[i * D4 + dc];
            p[i].x = v.x * m.x; p[i].y = v.y * m.y;
            p[i].z = v.z * m.z; p[i].w = v.w * m.w;
            float4 lp;
            lp.x = __log2f(p[i].x + EPSF);
            lp.y = __log2f(p[i].y + EPSF);
            lp.z = __log2f(p[i].z + EPSF);
            lp.w = __log2f(p[i].w + EPSF);
            ent[i] += p[i].x * lp.x + p[i].y * lp.y
                    + p[i].z * lp.z + p[i].w * lp.w;
        }
#pragma unroll
        for (int j = 0; j < N; j++) {
            float4 v = Q[j * D4 + dc];
            float4 m = M2[j * D4 + dc];
            float4 lq;
            lq.x = __log2f(v.x * m.x + EPSF);
            lq.y = __log2f(v.y * m.y + EPSF);
            lq.z = __log2f(v.z * m.z + EPSF);
            lq.w = __log2f(v.w * m.w + EPSF);
#pragma unroll
            for (int i = 0; i < N; i++) {
                cross[i][j] += p[i].x * lq.x + p[i].y * lq.y
                             + p[i].z * lq.z + p[i].w * lq.w;
            }
        }
    }

    // ---- block reduction of 20 accumulators ----
    __shared__ float red[NACC][NWARP];
    __shared__ float fin[NACC];
    const int lane = t & 31;
    const int wid  = t >> 5;

    float acc[NACC];
#pragma unroll
    for (int i = 0; i < N; i++) acc[i] = ent[i];
#pragma unroll
    for (int i = 0; i < N; i++)
#pragma unroll
        for (int j = 0; j < N; j++) acc[N + i * N + j] = cross[i][j];

#pragma unroll
    for (int k = 0; k < NACC; k++) {
        float v = acc[k];
#pragma unroll
        for (int off = 16; off > 0; off >>= 1)
            v += __shfl_down_sync(0xffffffffu, v, off);
        if (lane == 0) red[k][wid] = v;
    }
    __syncthreads();

    if (t < NACC) {
        float s = 0.f;
#pragma unroll
        for (int w = 0; w < NWARP; w++) s += red[t][w];
        fin[t] = s;
    }
    __syncthreads();

    if (t < N * N) {
        const int i = t >> 2;
        const float LN2 = 0.6931471805599453f;
        out[(size_t)b * (N * N) + t] = (fin[N + t] - fin[i]) * LN2;
    }
}

extern "C" void kernel_launch(void* const* d_in, const int* in_sizes, int n_in,
                              void* d_out, int out_size)
{
    const float4* in1 = (const float4*)d_in[0];
    const float4* m1  = (const float4*)d_in[1];
    const float4* in2 = (const float4*)d_in[2];
    const float4* m2  = (const float4*)d_in[3];
    float* out = (float*)d_out;

    const int bs = in_sizes[0] / (N * D);   // 2048
    negkl_kernel<<<bs, THREADS>>>(in1, m1, in2, m2, out);
}

// round 2
// speedup vs baseline: 1.1450x; 1.1450x over previous
#include <cuda_runtime.h>

#define EPSF 1e-9f

static constexpr int N = 4;           // n1 == n2 == 4
static constexpr int D = 4608;
static constexpr int D4 = D / 4;      // 1152 float4 per row
static constexpr int THREADS = 384;
static constexpr int ITERS = D4 / THREADS;  // 3
static constexpr int NWARP = THREADS / 32;  // 12
static constexpr int NACC = N + N * N;      // 20 accumulators

__global__ __launch_bounds__(THREADS, 3)
void negkl_kernel(const float4* __restrict__ in1, const float4* __restrict__ m1,
                  const float4* __restrict__ in2, const float4* __restrict__ m2,
                  float* __restrict__ out)
{
    const int b = blockIdx.x;
    const int t = threadIdx.x;
    const size_t base = (size_t)b * N * D4;
    const float4* P  = in1 + base;
    const float4* M1 = m1  + base;
    const float4* Q  = in2 + base;
    const float4* M2 = m2  + base;

    // ent[i]      = sum_d p_i * log2(p_i + eps)
    // cross[i][j] = sum_d p_i * log2(q_j + eps)
    // out[b,i,j]  = (cross[i][j] - ent[i]) * ln2
    float ent[N];
    float cross[N][N];
#pragma unroll
    for (int i = 0; i < N; i++) {
        ent[i] = 0.f;
#pragma unroll
        for (int j = 0; j < N; j++) cross[i][j] = 0.f;
    }

#pragma unroll
    for (int it = 0; it < ITERS; it++) {
        const int dc = it * THREADS + t;

        // ---- q tile first: 8 batched streaming loads -> lq[4] (16 regs) ----
        float4 lq[N];
#pragma unroll
        for (int j = 0; j < N; j++) {
            float4 v = __ldcs(&Q[j * D4 + dc]);
            float4 m = __ldcs(&M2[j * D4 + dc]);
            lq[j].x = __log2f(fmaf(v.x, m.x, EPSF));
            lq[j].y = __log2f(fmaf(v.y, m.y, EPSF));
            lq[j].z = __log2f(fmaf(v.z, m.z, EPSF));
            lq[j].w = __log2f(fmaf(v.w, m.w, EPSF));
        }

        // ---- stream p rows, consume immediately (no p[] array lives on) ----
#pragma unroll
        for (int i = 0; i < N; i++) {
            float4 v = __ldcs(&P[i * D4 + dc]);
            float4 m = __ldcs(&M1[i * D4 + dc]);
            float4 p;
            p.x = v.x * m.x; p.y = v.y * m.y;
            p.z = v.z * m.z; p.w = v.w * m.w;

            float4 lp;
            lp.x = __log2f(p.x + EPSF);
            lp.y = __log2f(p.y + EPSF);
            lp.z = __log2f(p.z + EPSF);
            lp.w = __log2f(p.w + EPSF);
            ent[i] = fmaf(p.x, lp.x, fmaf(p.y, lp.y,
                     fmaf(p.z, lp.z, fmaf(p.w, lp.w, ent[i]))));

#pragma unroll
            for (int j = 0; j < N; j++) {
                cross[i][j] = fmaf(p.x, lq[j].x, fmaf(p.y, lq[j].y,
                              fmaf(p.z, lq[j].z, fmaf(p.w, lq[j].w, cross[i][j]))));
            }
        }
    }

    // ---- block reduction of 20 accumulators ----
    __shared__ float red[NACC][NWARP];
    __shared__ float fin[NACC];
    const int lane = t & 31;
    const int wid  = t >> 5;

    float acc[NACC];
#pragma unroll
    for (int i = 0; i < N; i++) acc[i] = ent[i];
#pragma unroll
    for (int i = 0; i < N; i++)
#pragma unroll
        for (int j = 0; j < N; j++) acc[N + i * N + j] = cross[i][j];

#pragma unroll
    for (int k = 0; k < NACC; k++) {
        float v = acc[k];
#pragma unroll
        for (int off = 16; off > 0; off >>= 1)
            v += __shfl_down_sync(0xffffffffu, v, off);
        if (lane == 0) red[k][wid] = v;
    }
    __syncthreads();

    if (t < NACC) {
        float s = 0.f;
#pragma unroll
        for (int w = 0; w < NWARP; w++) s += red[t][w];
        fin[t] = s;
    }
    __syncthreads();

    if (t < N * N) {
        const int i = t >> 2;
        const float LN2 = 0.6931471805599453f;
        out[(size_t)b * (N * N) + t] = (fin[N + t] - fin[i]) * LN2;
    }
}

extern "C" void kernel_launch(void* const* d_in, const int* in_sizes, int n_in,
                              void* d_out, int out_size)
{
    const float4* in1 = (const float4*)d_in[0];
    const float4* m1  = (const float4*)d_in[1];
    const float4* in2 = (const float4*)d_in[2];
    const float4* m2  = (const float4*)d_in[3];
    float* out = (float*)d_out;

    const int bs = in_sizes[0] / (N * D);   // 2048
    negkl_kernel<<<bs, THREADS>>>(in1, m1, in2, m2, out);
}